// round 17
// baseline (speedup 1.0000x reference)
#include <cuda_runtime.h>
#include <math.h>

#define NN 50000
#define EE 800000
#define D  64

// ---------------- scratch (device globals; no allocations allowed) ----------
__device__ float g_q[NN * D];
__device__ float g_k[NN * D];
__device__ float g_v[NN * D];
__device__ float g_ep[(size_t)EE * D];   // 204.8 MB
__device__ float g_r [(size_t)EE * D];   // 204.8 MB  (EF @ W1c)
__device__ float g_nn[NN * D];
__device__ float g_pq[(size_t)NN * 2 * D]; // [node][0:64]=P=nn@W1a, [64:128]=Q=nn@W1b
__device__ int   g_hist[NN];
__device__ int   g_off[NN + 1];
__device__ int   g_cur[NN];
__device__ int   g_perm[EE];

// ---------------- kernels ---------------------------------------------------

__global__ void k_zero_hist() {
    int i = blockIdx.x * blockDim.x + threadIdx.x;
    if (i < NN) g_hist[i] = 0;
}

// q,k,v projections fused: one X-tile load, three weights. 32 rows per block.
__global__ __launch_bounds__(256) void k_qkv(
    const float* __restrict__ X,
    const float* __restrict__ Wq, const float* __restrict__ Wk,
    const float* __restrict__ Wv)
{
    __shared__ float Ws[D * D];
    __shared__ float Xs[32][D];
    int t = threadIdx.x;
    int row0 = blockIdx.x * 32;
    for (int i = t; i < 32 * D; i += 256) {
        int r = i >> 6, c = i & 63;
        int gr = row0 + r;
        Xs[r][c] = (gr < NN) ? X[gr * D + c] : 0.f;
    }
    const float* Wlist[3] = {Wq, Wk, Wv};
    float2* Olist[3] = {(float2*)g_q, (float2*)g_k, (float2*)g_v};
    int l = t & 31, ng = t >> 5;
    for (int m = 0; m < 3; m++) {
        __syncthreads();
        for (int i = t; i < D * D; i += 256) Ws[i] = Wlist[m][i];
        __syncthreads();
        const float2* Ws2 = (const float2*)Ws;
        float2* Y2 = Olist[m];
#pragma unroll
        for (int rr = 0; rr < 4; rr++) {
            int r = rr * 8 + ng;
            int gr = row0 + r;
            float a0 = 0.f, a1 = 0.f;
#pragma unroll
            for (int i = 0; i < D; i++) {
                float x = Xs[r][i];
                float2 w = Ws2[i * 32 + l];
                a0 += x * w.x; a1 += x * w.y;
            }
            if (gr < NN) Y2[gr * 32 + l] = make_float2(a0, a1);
        }
    }
}

// fused edge projections: g_ep = EF @ We  AND  g_r = EF @ W1c (W1 rows 128..191).
// One EF tile staged, 128 output cols. EE is an exact multiple of 32.
__global__ __launch_bounds__(256) void k_ep2(
    const float* __restrict__ EF, const float* __restrict__ We,
    const float* __restrict__ W1)
{
    __shared__ float Ws[D * 128];   // [k][c]: c<64 -> We[k][c]; c>=64 -> W1c[k][c-64]
    __shared__ float Xs[32][D];
    int t = threadIdx.x;
    for (int i = t; i < D * 128; i += 256) {
        int k = i >> 7, c = i & 127;
        Ws[i] = (c < 64) ? We[k * 64 + c] : W1[(128 + k) * 64 + (c - 64)];
    }
    size_t row0 = (size_t)blockIdx.x * 32;
    for (int i = t; i < 32 * D; i += 256) {
        int r = i >> 6, c = i & 63;
        Xs[r][c] = EF[(row0 + r) * D + c];
    }
    __syncthreads();
    int l = t & 31, ng = t >> 5;
    const float2* Ws2 = (const float2*)Ws;   // 64 float2 per k-row
    float2* EP2 = (float2*)g_ep;
    float2* R2  = (float2*)g_r;
#pragma unroll
    for (int rr = 0; rr < 4; rr++) {
        int r = rr * 8 + ng;
        float e0 = 0.f, e1 = 0.f, r0 = 0.f, r1 = 0.f;
#pragma unroll
        for (int k = 0; k < D; k++) {
            float x = Xs[r][k];
            float2 we = Ws2[k * 64 + l];
            float2 wr = Ws2[k * 64 + 32 + l];
            e0 += x * we.x; e1 += x * we.y;
            r0 += x * wr.x; r1 += x * wr.y;
        }
        EP2[(row0 + r) * 32 + l] = make_float2(e0, e1);
        R2 [(row0 + r) * 32 + l] = make_float2(r0, r1);
    }
}

// edge_index is int32 (JAX default; int64 in the reference is demoted).
__global__ void k_hist(const int* __restrict__ ei) {
    int e = blockIdx.x * blockDim.x + threadIdx.x;
    if (e < EE) {
        int tgt = ei[EE + e];
        if (tgt >= 0 && tgt < NN) atomicAdd(&g_hist[tgt], 1);
    }
}

// single-block exclusive scan over g_hist -> g_off, g_cur
__global__ __launch_bounds__(1024) void k_scan() {
    __shared__ int sdata[1024];
    __shared__ int s_carry;
    int t = threadIdx.x;
    if (t == 0) s_carry = 0;
    __syncthreads();
    for (int base = 0; base < NN; base += 1024) {
        int idx = base + t;
        int v = (idx < NN) ? g_hist[idx] : 0;
        sdata[t] = v;
        __syncthreads();
        for (int ofs = 1; ofs < 1024; ofs <<= 1) {
            int add = (t >= ofs) ? sdata[t - ofs] : 0;
            __syncthreads();
            sdata[t] += add;
            __syncthreads();
        }
        int excl = sdata[t] - v;
        if (idx < NN) {
            g_off[idx] = s_carry + excl;
            g_cur[idx] = s_carry + excl;
        }
        __syncthreads();
        if (t == 1023) s_carry += sdata[1023];
        __syncthreads();
    }
    if (t == 0) g_off[NN] = s_carry;
}

__global__ void k_scatter(const int* __restrict__ ei) {
    int e = blockIdx.x * blockDim.x + threadIdx.x;
    if (e < EE) {
        int tgt = ei[EE + e];
        if (tgt >= 0 && tgt < NN) {
            int pos = atomicAdd(&g_cur[tgt], 1);
            if (pos >= 0 && pos < EE) g_perm[pos] = e;
        }
    }
}

// one warp per node: softmax-attention aggregation + Wo + residual
#define EBUF 96
__global__ __launch_bounds__(256) void k_attn(
    const float* __restrict__ X, const int* __restrict__ ei,
    const float* __restrict__ Wo)
{
    __shared__ float Wos[D * D];
    __shared__ int   eb[8][EBUF];
    __shared__ float aggs[8][D];
    int t = threadIdx.x;
    for (int i = t; i < D * D; i += 256) Wos[i] = Wo[i];
    __syncthreads();

    int w = t >> 5, l = t & 31;
    int node = blockIdx.x * 8 + w;
    if (node >= NN) return;

    int o0 = g_off[node];
    int deg = g_off[node + 1] - o0;
    bool buf = (deg <= EBUF);
    if (buf) {
        for (int j = l; j < deg; j += 32) eb[w][j] = g_perm[o0 + j];
        __syncwarp();
        if (l == 0) {  // deterministic accumulation order
            for (int a = 1; a < deg; a++) {
                int key = eb[w][a]; int b = a - 1;
                while (b >= 0 && eb[w][b] > key) { eb[w][b + 1] = eb[w][b]; b--; }
                eb[w][b + 1] = key;
            }
        }
        __syncwarp();
    }

    const float2* q2  = (const float2*)g_q;
    const float2* k2  = (const float2*)g_k;
    const float2* v2  = (const float2*)g_v;
    const float2* ep2 = (const float2*)g_ep;

    float2 q = q2[node * 32 + l];
    float a0 = 0.f, a1 = 0.f, den = 0.f;
    for (int j = 0; j < deg; j++) {
        int e = buf ? eb[w][j] : g_perm[o0 + j];
        int s = ei[e];
        float2 epv = ep2[(size_t)e * 32 + l];
        float2 kv  = k2[s * 32 + l];
        float2 vv  = v2[s * 32 + l];
        float p = q.x * (kv.x + epv.x) + q.y * (kv.y + epv.y);
        p += __shfl_xor_sync(0xffffffffu, p, 1);
        p += __shfl_xor_sync(0xffffffffu, p, 2);
        p += __shfl_xor_sync(0xffffffffu, p, 4);   // 16-dim head dot done
        float ex = __expf(p * 0.25f);              // bounded scores: no max-shift
        den += ex;
        a0 += ex * (vv.x + epv.x);
        a1 += ex * (vv.y + epv.y);
    }
    float inv = (deg > 0) ? (1.0f / den) : 0.f;
    aggs[w][2 * l]     = a0 * inv;
    aggs[w][2 * l + 1] = a1 * inv;
    __syncwarp();

    float2 xr = ((const float2*)X)[node * 32 + l];
    float n0 = xr.x, n1 = xr.y;
    const float2* Wos2 = (const float2*)Wos;
#pragma unroll
    for (int i = 0; i < D; i++) {
        float a = aggs[w][i];
        float2 wv = Wos2[i * 32 + l];
        n0 += a * wv.x; n1 += a * wv.y;
    }
    ((float2*)g_nn)[node * 32 + l] = make_float2(n0, n1);
}

// node-side classifier projections: g_pq = nn @ [W1a | W1b]
// (W1a = W1 rows 0..63, W1b = W1 rows 64..127)
__global__ __launch_bounds__(256) void k_pq(const float* __restrict__ W1)
{
    __shared__ float Ws[D * 128];  // [k][c]: c<64 -> W1[k][c]; c>=64 -> W1[64+k][c-64]
    __shared__ float Xs[32][D];
    int t = threadIdx.x;
    for (int i = t; i < D * 128; i += 256) {
        int k = i >> 7, c = i & 127;
        Ws[i] = (c < 64) ? W1[k * 64 + c] : W1[(64 + k) * 64 + (c - 64)];
    }
    int row0 = blockIdx.x * 32;
    for (int i = t; i < 32 * D; i += 256) {
        int r = i >> 6, c = i & 63;
        int gr = row0 + r;
        Xs[r][c] = (gr < NN) ? g_nn[gr * D + c] : 0.f;
    }
    __syncthreads();
    int l = t & 31, ng = t >> 5;
    const float2* Ws2 = (const float2*)Ws;
    float2* PQ2 = (float2*)g_pq;
#pragma unroll
    for (int rr = 0; rr < 4; rr++) {
        int r = rr * 8 + ng;
        int gr = row0 + r;
        float p0 = 0.f, p1 = 0.f, q0 = 0.f, q1 = 0.f;
#pragma unroll
        for (int k = 0; k < D; k++) {
            float x = Xs[r][k];
            float2 wp = Ws2[k * 64 + l];
            float2 wq = Ws2[k * 64 + 32 + l];
            p0 += x * wp.x; p1 += x * wp.y;
            q0 += x * wq.x; q1 += x * wq.y;
        }
        if (gr < NN) {
            PQ2[(size_t)gr * 64 + l]      = make_float2(p0, p1);
            PQ2[(size_t)gr * 64 + 32 + l] = make_float2(q0, q1);
        }
    }
}

// streaming classifier: h = P[src] + Q[tgt] + R[e] + b1; gelu; out = h @ W2 + b2
// one warp per edge (8 edges per warp, 64 per block). EE = 12500 * 64.
__global__ __launch_bounds__(256) void k_cls2(
    const int* __restrict__ ei,
    const float* __restrict__ b1, const float* __restrict__ W2,
    const float* __restrict__ b2, float* __restrict__ out)
{
    int t = threadIdx.x, w = t >> 5, l = t & 31;
    const float2* PQ2 = (const float2*)g_pq;
    const float2* R2  = (const float2*)g_r;
    float2 bb  = ((const float2*)b1)[l];        // hidden cols 2l, 2l+1
    float2 w2a = ((const float2*)W2)[2 * l];    // W2 row 2l   (cols 0,1)
    float2 w2b = ((const float2*)W2)[2 * l + 1];// W2 row 2l+1 (cols 0,1)
    float b20 = b2[0], b21 = b2[1];
    int ebase = blockIdx.x * 64 + w * 8;
#pragma unroll
    for (int j = 0; j < 8; j++) {
        int e = ebase + j;
        int s = ei[e], g = ei[EE + e];
        float2 p = PQ2[(size_t)s * 64 + l];
        float2 q = PQ2[(size_t)g * 64 + 32 + l];
        float2 r = R2[(size_t)e * 32 + l];
        float h0 = p.x + q.x + r.x + bb.x;
        float h1 = p.y + q.y + r.y + bb.y;
        h0 = 0.5f * h0 * (1.f + erff(h0 * 0.70710678118654752440f));
        h1 = 0.5f * h1 * (1.f + erff(h1 * 0.70710678118654752440f));
        float o0 = h0 * w2a.x + h1 * w2b.x;
        float o1 = h0 * w2a.y + h1 * w2b.y;
#pragma unroll
        for (int ofs = 16; ofs; ofs >>= 1) {
            o0 += __shfl_xor_sync(0xffffffffu, o0, ofs);
            o1 += __shfl_xor_sync(0xffffffffu, o1, ofs);
        }
        if (l == 0) {
            out[(size_t)e * 2]     = o0 + b20;
            out[(size_t)e * 2 + 1] = o1 + b21;
        }
    }
}

// ---------------- launcher: kernel launches ONLY -----------------------------

extern "C" void kernel_launch(void* const* d_in, const int* in_sizes, int n_in,
                              void* d_out, int out_size)
{
    const float* X  = (const float*)d_in[0];
    const float* EF = (const float*)d_in[1];
    const int*   ei = (const int*)d_in[2];     // int32 edge_index (JAX default)
    const float* Wq = (const float*)d_in[3];
    const float* Wk = (const float*)d_in[4];
    const float* Wv = (const float*)d_in[5];
    const float* We = (const float*)d_in[6];
    const float* Wo = (const float*)d_in[7];
    const float* W1 = (const float*)d_in[8];
    const float* b1 = (const float*)d_in[9];
    const float* W2 = (const float*)d_in[10];
    const float* b2 = (const float*)d_in[11];
    float* out = (float*)d_out;

    // projections
    k_qkv<<<(NN + 31) / 32, 256>>>(X, Wq, Wk, Wv);
    k_ep2<<<EE / 32, 256>>>(EF, We, W1);       // ep AND R = EF@W1c in one pass

    // CSR by target
    k_zero_hist<<<(NN + 255) / 256, 256>>>();
    k_hist<<<(EE + 255) / 256, 256>>>(ei);
    k_scan<<<1, 1024>>>();
    k_scatter<<<(EE + 255) / 256, 256>>>(ei);

    // attention aggregation + residual
    k_attn<<<(NN + 7) / 8, 256>>>(X, ei, Wo);

    // node-side classifier projections, then streaming edge classifier
    k_pq<<<(NN + 31) / 32, 256>>>(W1);
    k_cls2<<<EE / 64, 256>>>(ei, b1, W2, b2, out);
}